// round 10
// baseline (speedup 1.0000x reference)
#include <cuda_runtime.h>
#include <math.h>

#define BATCH 32
#define H 512
#define W 512
#define NPIX (H*W)
#define EPSF 1e-4f
#define RSTRIP 16
#define NTHR 256

#define RGB_BLKS 32            // strips per batch = H / RSTRIP = 512/16 = 32
#define DEP_BLKS 16            // depth slices per batch
#define ARRIVALS (RGB_BLKS + DEP_BLKS)

// ---------------- per-block partial outputs (device globals) -------------------
// STATELESS DATA: every partial slot is unconditionally overwritten each
// invocation before it is read (same launch, ordered by the arrival counter).
// g_cnt is the only cross-block sync object: zero at launch entry, reset to
// zero by the finalizer before it exits, so every invocation sees 0.
__device__ int   g_hist_part[BATCH][RGB_BLKS][256];   // per-strip histograms
__device__ float g_lap_part [BATCH][RGB_BLKS][2];     // per-strip (sum, sumsq)
__device__ float g_dep_part [BATCH][DEP_BLKS][3];     // per-slice (n, sum, sumsq)
__device__ unsigned int g_cnt[BATCH];                 // zero-init; self-restoring

__device__ __forceinline__ float warp_sum(float v) {
    #pragma unroll
    for (int o = 16; o > 0; o >>= 1) v += __shfl_down_sync(0xffffffffu, v, o);
    return v;
}

// ---------------- single fused kernel ------------------------------------------
// grid: (ARRIVALS, BATCH), block: 256
//   blockIdx.x <  RGB_BLKS : rgb strip blockIdx.x of batch blockIdx.y
//   blockIdx.x >= RGB_BLKS : depth slice (blockIdx.x - RGB_BLKS)
// Last-arriving block per batch finalizes that batch.
__global__ __launch_bounds__(NTHR) void fused_kernel(
    const float* __restrict__ rgb,
    const float* __restrict__ depth,
    float* __restrict__ out)
{
    __shared__ float tile[(RSTRIP + 2) * W];   // gray strip + 1-row halo (36 KB)
    __shared__ int   shist[256];
    __shared__ float sred[24];
    __shared__ int   s_last;

    const int b   = blockIdx.y;
    const int bx  = blockIdx.x;
    const int tid = threadIdx.x;
    const int lane = tid & 31, w = tid >> 5;

    if (bx < RGB_BLKS) {
        // ================= RGB: gray -> laplacian partials + strip histogram ==
        const int rs = bx * RSTRIP;
        shist[tid] = 0;

        const float* base = rgb + (size_t)b * 3 * NPIX;
        const int W4 = W / 4;
        for (int v = tid; v < (RSTRIP + 2) * W4; v += NTHR) {
            int row = v / W4;
            int c4  = v - row * W4;
            int gr  = rs - 1 + row;
            float4 gout;
            if (gr >= 0 && gr < H) {
                const float4* rp = (const float4*)(base + (size_t)gr * W);
                const float4* gp = (const float4*)(base + NPIX + (size_t)gr * W);
                const float4* bp = (const float4*)(base + 2 * NPIX + (size_t)gr * W);
                float4 r  = __ldg(rp + c4);
                float4 g  = __ldg(gp + c4);
                float4 bl = __ldg(bp + c4);
                gout.x = 0.299f * r.x + 0.587f * g.x + 0.114f * bl.x;
                gout.y = 0.299f * r.y + 0.587f * g.y + 0.114f * bl.y;
                gout.z = 0.299f * r.z + 0.587f * g.z + 0.114f * bl.z;
                gout.w = 0.299f * r.w + 0.587f * g.w + 0.114f * bl.w;
            } else {
                gout.x = gout.y = gout.z = gout.w = 0.0f;
            }
            ((float4*)tile)[row * W4 + c4] = gout;
        }
        __syncthreads();

        float s1 = 0.0f, s2 = 0.0f;
        #pragma unroll
        for (int p = 0; p < (RSTRIP * W) / NTHR; p++) {
            int idx = tid + p * NTHR;
            int r = idx >> 9;
            int c = idx & (W - 1);
            const float* trow = tile + (r + 1) * W;
            float gc = trow[c];
            float lap = tile[r * W + c] + tile[(r + 2) * W + c] - 4.0f * gc;
            if (c > 0)     lap += trow[c - 1];
            if (c < W - 1) lap += trow[c + 1];
            s1 += lap;
            s2 += lap * lap;
            int bin = (int)fminf(fmaxf(gc * 255.0f, 0.0f), 255.0f);
            atomicAdd(&shist[bin], 1);   // block-local smem atomic only
        }

        s1 = warp_sum(s1);
        s2 = warp_sum(s2);
        if (lane == 0) { sred[w] = s1; sred[8 + w] = s2; }
        __syncthreads();
        if (w == 0) {
            float v1 = (lane < 8) ? sred[lane] : 0.0f;
            float v2 = (lane < 8) ? sred[8 + lane] : 0.0f;
            v1 = warp_sum(v1);
            v2 = warp_sum(v2);
            if (lane == 0) {
                g_lap_part[b][bx][0] = v1;   // plain store to private slot
                g_lap_part[b][bx][1] = v2;
            }
        }
        // strip histogram: plain store to this block's private slot
        g_hist_part[b][bx][tid] = shist[tid];
    } else {
        // ================= depth: masked partial sums =========================
        const int part = bx - RGB_BLKS;
        const float4* d4 = (const float4*)(depth + (size_t)b * NPIX);
        const int per = (NPIX / 4) / DEP_BLKS;   // 4096 float4 per slice

        float n = 0.0f, s1 = 0.0f, s2 = 0.0f;
        #pragma unroll 4
        for (int k = 0; k < per / NTHR; k++) {
            float4 v = __ldg(d4 + part * per + k * NTHR + tid);
            if (v.x > 0.0f) { n += 1.0f; s1 += v.x; s2 += v.x * v.x; }
            if (v.y > 0.0f) { n += 1.0f; s1 += v.y; s2 += v.y * v.y; }
            if (v.z > 0.0f) { n += 1.0f; s1 += v.z; s2 += v.z * v.z; }
            if (v.w > 0.0f) { n += 1.0f; s1 += v.w; s2 += v.w * v.w; }
        }
        n  = warp_sum(n);
        s1 = warp_sum(s1);
        s2 = warp_sum(s2);
        if (lane == 0) { sred[w] = n; sred[8 + w] = s1; sred[16 + w] = s2; }
        __syncthreads();
        if (w == 0) {
            float vn = (lane < 8) ? sred[lane] : 0.0f;
            float v1 = (lane < 8) ? sred[8 + lane] : 0.0f;
            float v2 = (lane < 8) ? sred[16 + lane] : 0.0f;
            vn = warp_sum(vn);
            v1 = warp_sum(v1);
            v2 = warp_sum(v2);
            if (lane == 0) {
                g_dep_part[b][part][0] = vn;   // plain store to private slot
                g_dep_part[b][part][1] = v1;
                g_dep_part[b][part][2] = v2;
            }
        }
    }

    // ================= arrival (release) =====================================
    __syncthreads();          // all partial stores of this block issued
    __threadfence();          // EVERY thread fences its own global stores
    __syncthreads();          // fences complete before the release arrive
    if (tid == 0) {
        unsigned int old = atomicAdd(&g_cnt[b], 1u);
        s_last = (old == ARRIVALS - 1) ? 1 : 0;
    }
    __syncthreads();
    if (!s_last) return;

    // ================= finalize (acquire) — last block for batch b ===========
    __threadfence();

    int cnt = 0;
    #pragma unroll
    for (int s = 0; s < RGB_BLKS; s++) cnt += __ldcg(&g_hist_part[b][s][tid]);
    float p = (float)cnt * (1.0f / (float)NPIX);
    float e = -p * log2f(p + EPSF);

    e = warp_sum(e);
    if (lane == 0) sred[w] = e;
    __syncthreads();
    if (tid == 0) {
        float entropy = 0.0f;
        #pragma unroll
        for (int i = 0; i < 8; i++) entropy += sred[i];

        float s1 = 0.0f, s2 = 0.0f, dn = 0.0f, ds1 = 0.0f, ds2 = 0.0f;
        #pragma unroll
        for (int s = 0; s < RGB_BLKS; s++) {
            s1 += __ldcg(&g_lap_part[b][s][0]);
            s2 += __ldcg(&g_lap_part[b][s][1]);
        }
        #pragma unroll
        for (int s = 0; s < DEP_BLKS; s++) {
            dn  += __ldcg(&g_dep_part[b][s][0]);
            ds1 += __ldcg(&g_dep_part[b][s][1]);
            ds2 += __ldcg(&g_dep_part[b][s][2]);
        }

        const float N = (float)NPIX;
        float lvar = (s2 - s1 * s1 / N) / (N - 1.0f);
        float clarity = lvar / (1000.0f + EPSF);
        float uniformity = 1.0f / (entropy + EPSF);
        float rgb_conf = 0.5f * (clarity + uniformity);

        float density = dn / N;
        float mean = ds1 / fmaxf(dn, 1.0f);
        float sq = ds2 - 2.0f * mean * ds1 + mean * mean * dn;
        float dvar = sq / fmaxf(dn - 1.0f, 1.0f);
        float dstd = sqrtf(fmaxf(dvar, 0.0f));
        float noise = (dn > 0.0f) ? dstd : 1.0f;
        float density_score = density / (10000.0f + EPSF);
        float noise_score = 1.0f / (noise + EPSF);
        float depth_conf = 0.5f * (density_score + noise_score);

        float denom = rgb_conf + depth_conf + EPSF;
        out[b]         = rgb_conf / denom;    // w_r
        out[BATCH + b] = depth_conf / denom;  // w_d

        g_cnt[b] = 0u;   // restore invariant: counter is 0 between invocations
    }
}

// ---------------- launch -------------------------------------------------------
extern "C" void kernel_launch(void* const* d_in, const int* in_sizes, int n_in,
                              void* d_out, int out_size) {
    const float* rgb   = (const float*)d_in[0];
    const float* depth = (const float*)d_in[1];
    float* out = (float*)d_out;

    dim3 grid(ARRIVALS, BATCH);
    fused_kernel<<<grid, NTHR>>>(rgb, depth, out);
}